// round 3
// baseline (speedup 1.0000x reference)
#include <cuda_runtime.h>
#include <math.h>

// AdaFace logit adjustment:
//   out = logits * 64, except out[r, labels[r]] = (cos(clip(acos(t)+g_ang,eps,pi-eps)) - g_add)*64
// B=1024 rows, C=100000 cols, fp32. HBM-streaming bound: 800 MB round trip.

#define B_ROWS 1024
#define SCALE 64.0f
#define MARGIN 0.4f
#define H_CONST 0.333f
#define EPS_CONST 1e-3f

// ---------------------------------------------------------------------------
// Kernel A: streaming scale, grid-stride with 4x float4 unroll per iteration.
// 102.4M floats = 25.6M float4 = 6.4M thread-iterations of 4.
// ---------------------------------------------------------------------------
__global__ void scale_kernel(const float4* __restrict__ in,
                             float4* __restrict__ out,
                             int n4) {
    int stride = gridDim.x * blockDim.x;
    int i = blockIdx.x * blockDim.x + threadIdx.x;

    // Main unrolled path: 4 independent float4 loads in flight per iteration.
    for (; i + 3 * stride < n4; i += 4 * stride) {
        float4 v0 = in[i];
        float4 v1 = in[i + stride];
        float4 v2 = in[i + 2 * stride];
        float4 v3 = in[i + 3 * stride];
        v0.x *= SCALE; v0.y *= SCALE; v0.z *= SCALE; v0.w *= SCALE;
        v1.x *= SCALE; v1.y *= SCALE; v1.z *= SCALE; v1.w *= SCALE;
        v2.x *= SCALE; v2.y *= SCALE; v2.z *= SCALE; v2.w *= SCALE;
        v3.x *= SCALE; v3.y *= SCALE; v3.z *= SCALE; v3.w *= SCALE;
        out[i]              = v0;
        out[i + stride]     = v1;
        out[i + 2 * stride] = v2;
        out[i + 3 * stride] = v3;
    }
    // Tail
    for (; i < n4; i += stride) {
        float4 v = in[i];
        v.x *= SCALE; v.y *= SCALE; v.z *= SCALE; v.w *= SCALE;
        out[i] = v;
    }
}

// ---------------------------------------------------------------------------
// Kernel B: single block, 1024 threads (one per row).
//  - clip norms, block-reduce mean and unbiased (ddof=1) std
//  - margin scaler, gather target logit, acos/cos margin, scatter *scaled*
//    adjusted target over d_out. Runs after kernel A in-stream, so the
//    scatter writes deterministically win.
// ---------------------------------------------------------------------------
__device__ __forceinline__ float block_sum_1024(float v, float* red) {
    // warp-level reduce
    #pragma unroll
    for (int o = 16; o > 0; o >>= 1)
        v += __shfl_down_sync(0xffffffffu, v, o);
    int lane = threadIdx.x & 31;
    int warp = threadIdx.x >> 5;
    if (lane == 0) red[warp] = v;
    __syncthreads();
    // 32 warps -> first warp reduces
    if (warp == 0) {
        v = red[lane];
        #pragma unroll
        for (int o = 16; o > 0; o >>= 1)
            v += __shfl_down_sync(0xffffffffu, v, o);
        if (lane == 0) red[0] = v;
    }
    __syncthreads();
    float r = red[0];
    __syncthreads();
    return r;
}

__global__ void margin_kernel(const float* __restrict__ logits,
                              const float* __restrict__ norms,
                              const int*   __restrict__ labels,
                              float* __restrict__ out,
                              int C) {
    __shared__ float red[32];

    int tid = threadIdx.x;

    // safe_norms = clip(norms, 1e-3, 100)
    float x = norms[tid];
    x = fminf(fmaxf(x, 1e-3f), 100.0f);

    // mean
    float mean = block_sum_1024(x, red) * (1.0f / B_ROWS);

    // unbiased std (ddof = 1)
    float d = x - mean;
    float ss = block_sum_1024(d * d, red);
    float stdv = sqrtf(ss * (1.0f / (B_ROWS - 1)));

    // margin scaler
    float ms = (x - mean) / (stdv + EPS_CONST) * H_CONST;
    ms = fminf(fmaxf(ms, -1.0f), 1.0f);

    float g_ang = -MARGIN * ms;
    float g_add = MARGIN + MARGIN * ms;

    // gather, adjust, scatter (scaled)
    int lbl = labels[tid];
    long long idx = (long long)tid * C + lbl;
    float t = logits[idx];

    float theta = acosf(t) + g_ang;
    theta = fminf(fmaxf(theta, EPS_CONST), (float)M_PI - EPS_CONST);
    float nt = (cosf(theta) - g_add) * SCALE;

    out[idx] = nt;
}

// ---------------------------------------------------------------------------
extern "C" void kernel_launch(void* const* d_in, const int* in_sizes, int n_in,
                              void* d_out, int out_size) {
    const float* logits = (const float*)d_in[0];
    const float* norms  = (const float*)d_in[1];
    const int*   labels = (const int*)d_in[2];
    float* out = (float*)d_out;

    int total = out_size;            // B*C elements (102,400,000)
    int C = total / B_ROWS;          // 100000
    int n4 = total / 4;              // 25,600,000 (C % 4 == 0)

    // Full-chip persistent-ish grid: 148 SMs * 8 blocks of 256 threads.
    int threads = 256;
    int blocks = 148 * 8;
    scale_kernel<<<blocks, threads>>>((const float4*)logits, (float4*)out, n4);
    margin_kernel<<<1, B_ROWS>>>(logits, norms, labels, out, C);
}

// round 4
// speedup vs baseline: 1.0291x; 1.0291x over previous
#include <cuda_runtime.h>
#include <math.h>

// AdaFace logit adjustment, fully fused single streaming kernel.
//   out = logits * 64, except out[r, labels[r]] = (cos(clip(acos(t)+g_ang,eps,pi-eps)) - g_add)*64
// B=1024 rows, C=100000 cols, fp32. 800 MB HBM round trip => ~100-120us floor.
//
// Fusion strategy: in != out, so the streaming thread that owns the target
// element already holds the raw logit in a register — no scattered gather and
// no second kernel. Each block owns a CONTIGUOUS chunk (<=2 rows), redundantly
// computes the norm stats (4KB, L2 broadcast), precomputes <=2 in-chunk target
// (index, g_ang, g_add) triples, and patches the lane inline during the stream.

#define B_ROWS   1024
#define SCALE    64.0f
#define MARGIN   0.4f
#define H_CONST  0.333f
#define EPS_CONST 1e-3f
#define THREADS  256
#define NBLOCKS  (148 * 8)
#define MAXT     4

__device__ __forceinline__ float block_sum_256(float v, float* red) {
    #pragma unroll
    for (int o = 16; o > 0; o >>= 1)
        v += __shfl_down_sync(0xffffffffu, v, o);
    int lane = threadIdx.x & 31;
    int warp = threadIdx.x >> 5;
    if (lane == 0) red[warp] = v;
    __syncthreads();
    if (warp == 0) {
        v = (lane < THREADS / 32) ? red[lane] : 0.0f;
        #pragma unroll
        for (int o = 4; o > 0; o >>= 1)
            v += __shfl_down_sync(0xffffffffu, v, o);
        if (lane == 0) red[0] = v;
    }
    __syncthreads();
    float r = red[0];
    __syncthreads();
    return r;
}

__global__ void __launch_bounds__(THREADS)
fused_kernel(const float4* __restrict__ in,
             float4* __restrict__ out,
             const float* __restrict__ norms,
             const int*   __restrict__ labels,
             int C, int n4) {
    __shared__ float red[THREADS / 32];
    __shared__ int   s_ntgt;
    __shared__ int   s_tgt_i4[MAXT];
    __shared__ int   s_tgt_c[MAXT];
    __shared__ float s_ga[MAXT];
    __shared__ float s_gd[MAXT];

    const int tid = threadIdx.x;

    // ---- block-contiguous chunk ----
    int chunk4 = (n4 + gridDim.x - 1) / gridDim.x;
    int i40 = blockIdx.x * chunk4;
    if (i40 >= n4) return;
    int i41 = min(n4, i40 + chunk4);

    // ---- norm stats (redundant per block; 4KB from L2) ----
    float xl[B_ROWS / THREADS];
    float acc = 0.0f;
    #pragma unroll
    for (int k = 0; k < B_ROWS / THREADS; k++) {
        float x = norms[tid + k * THREADS];
        x = fminf(fmaxf(x, 1e-3f), 100.0f);
        xl[k] = x;
        acc += x;
    }
    float mean = block_sum_256(acc, red) * (1.0f / B_ROWS);
    float vacc = 0.0f;
    #pragma unroll
    for (int k = 0; k < B_ROWS / THREADS; k++) {
        float d = xl[k] - mean;
        vacc += d * d;
    }
    float stdv = sqrtf(block_sum_256(vacc, red) * (1.0f / (B_ROWS - 1)));
    float inv_sh = H_CONST / (stdv + EPS_CONST);

    // ---- find targets inside this chunk (chunk spans <= 2 rows) ----
    if (tid == 0) s_ntgt = 0;
    __syncthreads();
    {
        int e0 = i40 * 4;
        int e1 = i41 * 4;                 // exclusive; fits int (<= 102.4M)
        int r0 = e0 / C;
        int r1 = (e1 - 1) / C;
        int nrows = r1 - r0 + 1;          // 1 or 2
        if (tid < nrows && tid < MAXT) {
            int r = r0 + tid;
            int lbl = labels[r];
            int tgt = r * C + lbl;        // < 102.4M, fits int
            if (tgt >= e0 && tgt < e1) {
                float x = fminf(fmaxf(norms[r], 1e-3f), 100.0f);
                float ms = (x - mean) * inv_sh;
                ms = fminf(fmaxf(ms, -1.0f), 1.0f);
                int slot = atomicAdd(&s_ntgt, 1);
                s_tgt_i4[slot] = tgt >> 2;
                s_tgt_c[slot]  = tgt & 3;
                s_ga[slot]     = -MARGIN * ms;
                s_gd[slot]     = MARGIN + MARGIN * ms;
            }
        }
    }
    __syncthreads();
    const int ntgt = s_ntgt;

    // ---- stream the chunk ----
    auto patch = [&](float4& v, int i4) {
        for (int t = 0; t < ntgt; t++) {
            if (i4 == s_tgt_i4[t]) {
                int c = s_tgt_c[t];
                float tv = (c == 0) ? v.x : (c == 1) ? v.y : (c == 2) ? v.z : v.w;
                float theta = acosf(tv) + s_ga[t];
                theta = fminf(fmaxf(theta, EPS_CONST), (float)M_PI - EPS_CONST);
                float nt = cosf(theta) - s_gd[t];
                switch (c) {
                    case 0: v.x = nt; break;
                    case 1: v.y = nt; break;
                    case 2: v.z = nt; break;
                    default: v.w = nt; break;
                }
            }
        }
    };

    int i = i40 + tid;
    for (; i + 3 * THREADS < i41; i += 4 * THREADS) {
        float4 v0 = __ldcs(&in[i]);
        float4 v1 = __ldcs(&in[i + THREADS]);
        float4 v2 = __ldcs(&in[i + 2 * THREADS]);
        float4 v3 = __ldcs(&in[i + 3 * THREADS]);
        if (ntgt) {
            patch(v0, i);
            patch(v1, i + THREADS);
            patch(v2, i + 2 * THREADS);
            patch(v3, i + 3 * THREADS);
        }
        v0.x *= SCALE; v0.y *= SCALE; v0.z *= SCALE; v0.w *= SCALE;
        v1.x *= SCALE; v1.y *= SCALE; v1.z *= SCALE; v1.w *= SCALE;
        v2.x *= SCALE; v2.y *= SCALE; v2.z *= SCALE; v2.w *= SCALE;
        v3.x *= SCALE; v3.y *= SCALE; v3.z *= SCALE; v3.w *= SCALE;
        __stcs(&out[i],               v0);
        __stcs(&out[i + THREADS],     v1);
        __stcs(&out[i + 2 * THREADS], v2);
        __stcs(&out[i + 3 * THREADS], v3);
    }
    for (; i < i41; i += THREADS) {
        float4 v = __ldcs(&in[i]);
        if (ntgt) patch(v, i);
        v.x *= SCALE; v.y *= SCALE; v.z *= SCALE; v.w *= SCALE;
        __stcs(&out[i], v);
    }
}

extern "C" void kernel_launch(void* const* d_in, const int* in_sizes, int n_in,
                              void* d_out, int out_size) {
    const float* logits = (const float*)d_in[0];
    const float* norms  = (const float*)d_in[1];
    const int*   labels = (const int*)d_in[2];
    float* out = (float*)d_out;

    int total = out_size;            // B*C = 102,400,000
    int C = total / B_ROWS;          // 100000
    int n4 = total / 4;              // 25,600,000 (C % 4 == 0)

    fused_kernel<<<NBLOCKS, THREADS>>>((const float4*)logits, (float4*)out,
                                       norms, labels, C, n4);
}